// round 9
// baseline (speedup 1.0000x reference)
#include <cuda_runtime.h>
#include <cuda_fp16.h>
#include <math.h>

#define IN_DIM 128
#define HID    64
#define MAXN   100000
#define MAXE   1600000

// ---------------- scratch (static device globals; no allocation) ----------------
__device__ __align__(16) float  g_h   [(size_t)MAXN * HID];  // layer input (fp32)
__device__ __align__(16) __half g_hw_h[(size_t)MAXN * HID];  // h @ W (fp16 storage)
__device__ float g_dinv[MAXN];
__device__ int   g_cnt[MAXN];        // in-degree (without self loop)
__device__ int   g_base[MAXN];       // CSR row start
__device__ int   g_cursor[MAXN];     // fill cursor
__device__ int   g_total;            // atomic allocation counter
__device__ __align__(16) int2 g_csr[MAXE];  // (src, nrm bits) per CSR slot

// ================= CSR build (scan-free: atomic row allocation) =================
__global__ void zero_cnt_kernel(int n) {
    int i = blockIdx.x * blockDim.x + threadIdx.x;
    if (i < n) g_cnt[i] = 0;
    if (i == 0) g_total = 0;
}

__global__ void hist_kernel(const int* __restrict__ dst, int E) {
    int e = blockIdx.x * blockDim.x + threadIdx.x;
    if (e < E) atomicAdd(&g_cnt[dst[e]], 1);
}

__global__ void alloc_base_kernel(int n) {
    int i = blockIdx.x * blockDim.x + threadIdx.x;
    if (i >= n) return;
    int c = g_cnt[i];
    int base = atomicAdd(&g_total, c);   // contiguous row, arbitrary placement
    g_base[i]   = base;
    g_cursor[i] = base;
    g_dinv[i]   = rsqrtf((float)c + 1.0f);   // deg of A+I
}

// store fully-premultiplied edge norm: nrm = dinv[src] * dinv[dst]
__global__ void fill_kernel(const int* __restrict__ src,
                            const int* __restrict__ dst, int E) {
    int e = blockIdx.x * blockDim.x + threadIdx.x;
    if (e >= E) return;
    int d = dst[e];
    int s = src[e];
    int pos = atomicAdd(&g_cursor[d], 1);
    float nrm = g_dinv[s] * g_dinv[d];
    g_csr[pos] = make_int2(s, __float_as_int(nrm));   // one 8B store
}

// ================= register-blocked GEMM: 8 rows x 4 cols per thread ============
// 64-row tiles, 128 threads. Per k-step: 8 scalar LDS + 1 LDS.128 per 32 FMA.
// As stride 65: 8-row groups -> lane0/lane16 offset = 520 words = bank 8 (no conflict).
template<int K>
__device__ __forceinline__ void gemm_rb8_compute(const float* __restrict__ A,
                                                 const float* __restrict__ W,
                                                 int n, int row0, float4* acc) {
    __shared__ float  As[64][65];    // 16.25 KB
    __shared__ float4 Ws[64][16];    // 16 KB

    const int t  = threadIdx.x;      // 0..127
    const int tr = (t >> 4) << 3;    // 0,8,...,56
    const int tc = t & 15;

    for (int kh = 0; kh < K; kh += 64) {
        #pragma unroll
        for (int i = t; i < 1024; i += 128) {
            int k = i >> 4, c = i & 15;
            Ws[k][c] = ((const float4*)(W + (size_t)(kh + k) * HID))[c];
        }
        #pragma unroll
        for (int i = t; i < 1024; i += 128) {
            int r = i >> 4, c = i & 15;
            float4 v = make_float4(0.f,0.f,0.f,0.f);
            int row = row0 + r;
            if (row < n) v = *(const float4*)(A + (size_t)row * K + kh + c * 4);
            As[r][c*4+0] = v.x; As[r][c*4+1] = v.y;
            As[r][c*4+2] = v.z; As[r][c*4+3] = v.w;
        }
        __syncthreads();

        #pragma unroll 8
        for (int k = 0; k < 64; k++) {
            float4 w = Ws[k][tc];
            #pragma unroll
            for (int j = 0; j < 8; j++) {
                float x = As[tr + j][k];
                acc[j].x += x * w.x; acc[j].y += x * w.y;
                acc[j].z += x * w.z; acc[j].w += x * w.w;
            }
        }
        __syncthreads();
    }
}

// feature_pre: x[n,128] @ W_pre + b -> g_h (fp32). Globals referenced in device
// code only (GB300 ATS silently dereferences host-side shadow symbols).
__global__ void gemm_pre_rb_kernel(const float* __restrict__ x,
                                   const float* __restrict__ W,
                                   const float* __restrict__ bias, int n) {
    float4 acc[8];
    #pragma unroll
    for (int j = 0; j < 8; j++) acc[j] = make_float4(0.f,0.f,0.f,0.f);
    int row0 = blockIdx.x * 64;
    gemm_rb8_compute<IN_DIM>(x, W, n, row0, acc);

    const int tr = (threadIdx.x >> 4) << 3, tc = threadIdx.x & 15;
    float4 b = ((const float4*)bias)[tc];
    #pragma unroll
    for (int j = 0; j < 8; j++) {
        int row = row0 + tr + j;
        if (row < n) {
            float4 r;
            r.x = acc[j].x + b.x; r.y = acc[j].y + b.y;
            r.z = acc[j].z + b.z; r.w = acc[j].w + b.w;
            ((float4*)(g_h + (size_t)row * HID))[tc] = r;
        }
    }
}

// layer GEMM: g_h[n,64] @ W -> g_hw_h (fp16 storage for gather bandwidth)
__global__ void gemm_layer_rb_kernel(const float* __restrict__ W, int n) {
    float4 acc[8];
    #pragma unroll
    for (int j = 0; j < 8; j++) acc[j] = make_float4(0.f,0.f,0.f,0.f);
    int row0 = blockIdx.x * 64;
    gemm_rb8_compute<HID>(g_h, W, n, row0, acc);

    const int tr = (threadIdx.x >> 4) << 3, tc = threadIdx.x & 15;
    #pragma unroll
    for (int j = 0; j < 8; j++) {
        int row = row0 + tr + j;
        if (row < n) {
            __half2 h0 = __floats2half2_rn(acc[j].x, acc[j].y);
            __half2 h1 = __floats2half2_rn(acc[j].z, acc[j].w);
            uint2 pack = make_uint2(*reinterpret_cast<const unsigned*>(&h0),
                                    *reinterpret_cast<const unsigned*>(&h1));
            ((uint2*)(g_hw_h + (size_t)row * HID))[tc] = pack;
        }
    }
}

// ================= fused gather (warp per node, MLP=4) =================
// acc = hw[node]*dinv^2 + b  +  sum_{e: dst=node} hw[src_e] * nrm_e
// 4x unrolled: 4 independent LDGs issued before any consuming FFMA.
template<bool FINAL>
__global__ void gather_kernel(const float* __restrict__ bias,
                              float* __restrict__ out, int n) {
    int w    = (blockIdx.x * blockDim.x + threadIdx.x) >> 5;
    int lane = threadIdx.x & 31;
    if (w >= n) return;

    const __half2* hw2 = (const __half2*)g_hw_h;   // row = 32 half2
    float dd = g_dinv[w];
    float2 self = __half22float2(hw2[(size_t)w * 32 + lane]);
    float2 b    = ((const float2*)bias)[lane];
    float2 acc;
    acc.x = self.x * dd * dd + b.x;
    acc.y = self.y * dd * dd + b.y;

    int jbeg = g_base[w];
    int deg  = g_cnt[w];
    for (int j0 = 0; j0 < deg; j0 += 32) {
        int   s  = 0;
        float nm = 0.f;
        if (j0 + lane < deg) {
            int2 rec = g_csr[jbeg + j0 + lane];
            s  = rec.x;
            nm = __int_as_float(rec.y);
        }
        int m = min(32, deg - j0);
        int i = 0;
        for (; i + 4 <= m; i += 4) {
            int s0 = __shfl_sync(0xffffffffu, s, i+0);
            int s1 = __shfl_sync(0xffffffffu, s, i+1);
            int s2 = __shfl_sync(0xffffffffu, s, i+2);
            int s3 = __shfl_sync(0xffffffffu, s, i+3);
            float n0 = __shfl_sync(0xffffffffu, nm, i+0);
            float n1 = __shfl_sync(0xffffffffu, nm, i+1);
            float n2 = __shfl_sync(0xffffffffu, nm, i+2);
            float n3 = __shfl_sync(0xffffffffu, nm, i+3);
            float2 v0 = __half22float2(hw2[(size_t)s0 * 32 + lane]);
            float2 v1 = __half22float2(hw2[(size_t)s1 * 32 + lane]);
            float2 v2 = __half22float2(hw2[(size_t)s2 * 32 + lane]);
            float2 v3 = __half22float2(hw2[(size_t)s3 * 32 + lane]);
            acc.x += v0.x * n0; acc.y += v0.y * n0;
            acc.x += v1.x * n1; acc.y += v1.y * n1;
            acc.x += v2.x * n2; acc.y += v2.y * n2;
            acc.x += v3.x * n3; acc.y += v3.y * n3;
        }
        for (; i < m; i++) {
            int   si = __shfl_sync(0xffffffffu, s,  i);
            float ni = __shfl_sync(0xffffffffu, nm, i);
            float2 v = __half22float2(hw2[(size_t)si * 32 + lane]);
            acc.x += v.x * ni;
            acc.y += v.y * ni;
        }
    }

    if (!FINAL) {
        float2 r;
        r.x = fmaxf(acc.x, 0.f);
        r.y = fmaxf(acc.y, 0.f);
        ((float2*)g_h)[(size_t)w * 32 + lane] = r;
    } else {
        float ss = acc.x * acc.x + acc.y * acc.y;
        #pragma unroll
        for (int o = 16; o; o >>= 1) ss += __shfl_xor_sync(0xffffffffu, ss, o);
        float sc = 1.0f / fmaxf(sqrtf(ss), 1e-12f);
        float2 r; r.x = acc.x * sc; r.y = acc.y * sc;
        ((float2*)out)[(size_t)w * 32 + lane] = r;
    }
}

// ================= host launcher =================
extern "C" void kernel_launch(void* const* d_in, const int* in_sizes, int n_in,
                              void* d_out, int out_size) {
    const float* x     = (const float*)d_in[0];
    const int*   ei    = (const int*)d_in[1];   // int32 (JAX x64 disabled)
    const float* W_pre = (const float*)d_in[2];
    const float* b_pre = (const float*)d_in[3];
    const float* Wl[3] = {(const float*)d_in[4], (const float*)d_in[6], (const float*)d_in[8]};
    const float* Bl[3] = {(const float*)d_in[5], (const float*)d_in[7], (const float*)d_in[9]};
    float* out = (float*)d_out;

    int n = in_sizes[0] / IN_DIM;    // 100000
    int E = in_sizes[1] / 2;         // 1600000
    const int* src_idx = ei;
    const int* dst_idx = ei + E;

    // --- CSR build (scan-free) ---
    zero_cnt_kernel<<<(n + 255) / 256, 256>>>(n);
    hist_kernel<<<(E + 255) / 256, 256>>>(dst_idx, E);
    alloc_base_kernel<<<(n + 255) / 256, 256>>>(n);
    fill_kernel<<<(E + 255) / 256, 256>>>(src_idx, dst_idx, E);

    int gemm_blocks   = (n + 63) / 64;
    int gather_blocks = (n * 32 + 255) / 256;

    // feature_pre: x[n,128] @ W_pre + b_pre -> g_h
    gemm_pre_rb_kernel<<<gemm_blocks, 128>>>(x, W_pre, b_pre, n);

    // layer 1
    gemm_layer_rb_kernel<<<gemm_blocks, 128>>>(Wl[0], n);
    gather_kernel<false><<<gather_blocks, 256>>>(Bl[0], nullptr, n);
    // layer 2
    gemm_layer_rb_kernel<<<gemm_blocks, 128>>>(Wl[1], n);
    gather_kernel<false><<<gather_blocks, 256>>>(Bl[1], nullptr, n);
    // layer 3 (+ L2 normalize)
    gemm_layer_rb_kernel<<<gemm_blocks, 128>>>(Wl[2], n);
    gather_kernel<true><<<gather_blocks, 256>>>(Bl[2], out, n);
}